// round 1
// baseline (speedup 1.0000x reference)
#include <cuda_runtime.h>
#include <cuda_bf16.h>
#include <math.h>

#define NN 100000
#define EE 1600000
#define DIM 64
#define HEADS 8
#define HIDDEN 256

// -------- scratch (device globals; no allocation allowed) --------
__device__ __align__(16) float g_h[NN * DIM];        // node features after w_in
__device__ __align__(16) float g_su[NN * HEADS];
__device__ __align__(16) float g_sv[NN * HEADS];
__device__ __align__(16) float g_denom[NN * HEADS];  // softmax denominators (unnormalized)
__device__ __align__(16) float g_aggr[NN * DIM];     // unnormalized weighted message sums
__device__ float g_W2[2 * HEADS];                    // w_edge @ w_att_e  [2,8]
__device__ float g_c[HEADS];                         // b_edge @ w_att_e + b_att_e

// -------- tiny prep: fold edge-feature path into 2x8 --------
__global__ void k_prep(const float* __restrict__ w_edge, const float* __restrict__ b_edge,
                       const float* __restrict__ w_att_e, const float* __restrict__ b_att_e) {
    int t = threadIdx.x;
    if (t < 16) {
        int i = t >> 3, hh = t & 7;
        float s = 0.f;
        for (int k = 0; k < DIM; k++) s = fmaf(w_edge[i * DIM + k], w_att_e[k * HEADS + hh], s);
        g_W2[t] = s;
    } else if (t < 24) {
        int hh = t - 16;
        float s = b_att_e[hh];
        for (int k = 0; k < DIM; k++) s = fmaf(b_edge[k], w_att_e[k * HEADS + hh], s);
        g_c[hh] = s;
    }
}

// -------- node input: h = x@w_in + b_in ; su = h@w_att_u + b ; sv = h@w_att_v --------
// 256 threads = 4 nodes x 64 dims. w_in column held in registers per thread.
__global__ __launch_bounds__(256) void k_node_in(
    const float* __restrict__ x, const float* __restrict__ w_in, const float* __restrict__ b_in,
    const float* __restrict__ wu, const float* __restrict__ bu, const float* __restrict__ wv) {
    __shared__ float xs[4 * DIM];
    __shared__ float hs[4 * DIM];
    __shared__ float wus[DIM * HEADS];
    __shared__ float wvs[DIM * HEADS];

    int t = threadIdx.x;
    int nd = t >> 6, j = t & 63;

    for (int i = t; i < DIM * HEADS; i += 256) { wus[i] = wu[i]; wvs[i] = wv[i]; }

    float wcol[DIM];
#pragma unroll
    for (int k = 0; k < DIM; k++) wcol[k] = w_in[k * DIM + j];
    float bj = b_in[j];
    __syncthreads();

    int ngroups = (NN + 3) / 4;
    for (int g = blockIdx.x; g < ngroups; g += gridDim.x) {
        int n = g * 4 + nd;
        if (n < NN) xs[nd * DIM + j] = x[n * DIM + j];
        __syncthreads();
        if (n < NN) {
            float acc = bj;
            const float4* xp = (const float4*)(xs + nd * DIM);
#pragma unroll
            for (int k4 = 0; k4 < 16; k4++) {
                float4 xv = xp[k4];
                acc = fmaf(xv.x, wcol[4 * k4 + 0], acc);
                acc = fmaf(xv.y, wcol[4 * k4 + 1], acc);
                acc = fmaf(xv.z, wcol[4 * k4 + 2], acc);
                acc = fmaf(xv.w, wcol[4 * k4 + 3], acc);
            }
            hs[nd * DIM + j] = acc;
            g_h[n * DIM + j] = acc;
        }
        __syncthreads();
        if (n < NN && j < 16) {
            int hh = j & 7;
            const float* wm = (j < 8) ? wus : wvs;
            float s = (j < 8) ? bu[hh] : 0.f;
#pragma unroll 8
            for (int k = 0; k < DIM; k++) s = fmaf(hs[nd * DIM + k], wm[k * HEADS + hh], s);
            if (j < 8) g_su[n * HEADS + hh] = s;
            else       g_sv[n * HEADS + hh] = s;
        }
        __syncthreads();
    }
}

// -------- single edge pass: scores -> exp -> denom & weighted message scatter --------
__global__ __launch_bounds__(256) void k_edge(const int* __restrict__ src, const int* __restrict__ dst,
                                              const float* __restrict__ ef) {
    __shared__ float W2s[16];
    __shared__ float cs[8];
    if (threadIdx.x < 16) W2s[threadIdx.x] = g_W2[threadIdx.x];
    if (threadIdx.x < 8)  cs[threadIdx.x] = g_c[threadIdx.x];
    __syncthreads();

    for (int e = blockIdx.x * blockDim.x + threadIdx.x; e < EE; e += gridDim.x * blockDim.x) {
        int s = src[e], d = dst[e];
        float2 f = ((const float2*)ef)[e];
        const float4* sup = (const float4*)(g_su + s * HEADS);
        const float4* svp = (const float4*)(g_sv + d * HEADS);
        float4 u0 = sup[0], u1 = sup[1], v0 = svp[0], v1 = svp[1];
        float tt[8];
        tt[0] = u0.x + v0.x; tt[1] = u0.y + v0.y; tt[2] = u0.z + v0.z; tt[3] = u0.w + v0.w;
        tt[4] = u1.x + v1.x; tt[5] = u1.y + v1.y; tt[6] = u1.z + v1.z; tt[7] = u1.w + v1.w;
#pragma unroll
        for (int hh = 0; hh < 8; hh++) {
            float v = tt[hh] + f.x * W2s[hh] + f.y * W2s[8 + hh] + cs[hh];
            v = fmaxf(v, 0.2f * v);          // LeakyReLU(0.2)
            tt[hh] = __expf(v);              // no max-subtraction needed (small scores)
        }
        float4* dnp = (float4*)(g_denom + d * HEADS);
        atomicAdd(dnp + 0, make_float4(tt[0], tt[1], tt[2], tt[3]));
        atomicAdd(dnp + 1, make_float4(tt[4], tt[5], tt[6], tt[7]));

        const float4* hp = (const float4*)(g_h + s * DIM);
        float4* op = (float4*)(g_aggr + d * DIM);
#pragma unroll
        for (int q = 0; q < 16; q++) {
            float4 hv = hp[q];
            int b = (q & 1) * 4;  // head index = column & 7 (reshape [N, hd, H])
            atomicAdd(op + q, make_float4(hv.x * tt[b + 0], hv.y * tt[b + 1],
                                          hv.z * tt[b + 2], hv.w * tt[b + 3]));
        }
    }
}

// -------- normalize + FFN: out = gelu(agg@w1+b1)@w2 + b2 --------
// 8 nodes / iteration; weight columns live in registers; split-K for the 2nd GEMM.
#define FFN 8
__global__ __launch_bounds__(256) void k_ff(
    const float* __restrict__ w1, const float* __restrict__ b1,
    const float* __restrict__ w2, const float* __restrict__ b2,
    float* __restrict__ out) {
    __shared__ float aggs[FFN * DIM];         // 2 KB
    __shared__ float hids[FFN * HIDDEN];      // 8 KB
    __shared__ float psum[4 * FFN * DIM];     // 8 KB
    __shared__ float b2s[DIM];

    int t = threadIdx.x;
    int j = t & 63, gq = t >> 6;

    float w1reg[DIM];
#pragma unroll
    for (int k = 0; k < DIM; k++) w1reg[k] = w1[k * HIDDEN + t];
    float w2reg[DIM];
#pragma unroll
    for (int k = 0; k < DIM; k++) w2reg[k] = w2[(gq * DIM + k) * DIM + j];
    float b1t = b1[t];
    if (t < DIM) b2s[t] = b2[t];
    __syncthreads();

    int ngroups = (NN + FFN - 1) / FFN;
    for (int g = blockIdx.x; g < ngroups; g += gridDim.x) {
        int n0 = g * FFN;
        // load + normalize aggregated messages
#pragma unroll
        for (int r = 0; r < 2; r++) {
            int idx = t + r * 256;
            int nd = idx >> 6, jj = idx & 63;
            int n = n0 + nd;
            float v = 0.f;
            if (n < NN) {
                float dn = g_denom[n * HEADS + (jj & 7)];
                v = g_aggr[n * DIM + jj] / fmaxf(dn, 1e-12f);
            }
            aggs[idx] = v;
        }
        __syncthreads();
        // GEMM1: hidden unit t for all 8 nodes
        float hacc[FFN];
#pragma unroll
        for (int q = 0; q < FFN; q++) hacc[q] = b1t;
#pragma unroll
        for (int k4 = 0; k4 < 16; k4++) {
#pragma unroll
            for (int q = 0; q < FFN; q++) {
                float4 av = *(const float4*)(aggs + q * DIM + 4 * k4);
                hacc[q] = fmaf(av.x, w1reg[4 * k4 + 0], hacc[q]);
                hacc[q] = fmaf(av.y, w1reg[4 * k4 + 1], hacc[q]);
                hacc[q] = fmaf(av.z, w1reg[4 * k4 + 2], hacc[q]);
                hacc[q] = fmaf(av.w, w1reg[4 * k4 + 3], hacc[q]);
            }
        }
#pragma unroll
        for (int q = 0; q < FFN; q++) {
            float v = hacc[q];
            v = 0.5f * v * (1.0f + erff(v * 0.70710678118654752f));  // exact gelu
            hids[q * HIDDEN + t] = v;
        }
        __syncthreads();
        // GEMM2 (split-K over 4 groups of 64)
        float oacc[FFN];
#pragma unroll
        for (int q = 0; q < FFN; q++) oacc[q] = 0.f;
#pragma unroll
        for (int k4 = 0; k4 < 16; k4++) {
#pragma unroll
            for (int q = 0; q < FFN; q++) {
                float4 hv = *(const float4*)(hids + q * HIDDEN + gq * DIM + 4 * k4);
                oacc[q] = fmaf(hv.x, w2reg[4 * k4 + 0], oacc[q]);
                oacc[q] = fmaf(hv.y, w2reg[4 * k4 + 1], oacc[q]);
                oacc[q] = fmaf(hv.z, w2reg[4 * k4 + 2], oacc[q]);
                oacc[q] = fmaf(hv.w, w2reg[4 * k4 + 3], oacc[q]);
            }
        }
#pragma unroll
        for (int q = 0; q < FFN; q++) psum[(gq * FFN + q) * DIM + j] = oacc[q];
        __syncthreads();
        // reduce split-K partials and store
#pragma unroll
        for (int r = 0; r < 2; r++) {
            int idx = t + r * 256;
            int q = idx >> 6, jj = idx & 63;
            int n = n0 + q;
            if (n < NN) {
                float s = b2s[jj];
                s += psum[(0 * FFN + q) * DIM + jj];
                s += psum[(1 * FFN + q) * DIM + jj];
                s += psum[(2 * FFN + q) * DIM + jj];
                s += psum[(3 * FFN + q) * DIM + jj];
                out[n * DIM + jj] = s;
            }
        }
        __syncthreads();
    }
}

extern "C" void kernel_launch(void* const* d_in, const int* in_sizes, int n_in,
                              void* d_out, int out_size) {
    const float* x       = (const float*)d_in[0];
    const float* ef      = (const float*)d_in[1];
    const float* w_in    = (const float*)d_in[2];
    const float* b_in    = (const float*)d_in[3];
    const float* w_edge  = (const float*)d_in[4];
    const float* b_edge  = (const float*)d_in[5];
    const float* w_att_u = (const float*)d_in[6];
    const float* b_att_u = (const float*)d_in[7];
    const float* w_att_v = (const float*)d_in[8];
    const float* w_att_e = (const float*)d_in[9];
    const float* b_att_e = (const float*)d_in[10];
    const float* w_ff1   = (const float*)d_in[11];
    const float* b_ff1   = (const float*)d_in[12];
    const float* w_ff2   = (const float*)d_in[13];
    const float* b_ff2   = (const float*)d_in[14];
    const int*   src     = (const int*)d_in[15];
    const int*   dst     = (const int*)d_in[16];
    float* out = (float*)d_out;

    void *p_denom = nullptr, *p_aggr = nullptr;
    cudaGetSymbolAddress(&p_denom, g_denom);
    cudaGetSymbolAddress(&p_aggr, g_aggr);
    cudaMemsetAsync(p_denom, 0, (size_t)NN * HEADS * sizeof(float), 0);
    cudaMemsetAsync(p_aggr, 0, (size_t)NN * DIM * sizeof(float), 0);

    k_prep<<<1, 32>>>(w_edge, b_edge, w_att_e, b_att_e);
    k_node_in<<<2048, 256>>>(x, w_in, b_in, w_att_u, b_att_u, w_att_v);
    k_edge<<<(EE + 255) / 256, 256>>>(src, dst, ef);
    k_ff<<<592, 256>>>(w_ff1, b_ff1, w_ff2, b_ff2, out);
}

// round 2
// speedup vs baseline: 1.1002x; 1.1002x over previous
#include <cuda_runtime.h>
#include <cuda_bf16.h>
#include <math.h>

#define NN 100000
#define EE 1600000
#define DIM 64
#define HEADS 8
#define HIDDEN 256

// -------- scratch (device globals; no allocation allowed) --------
__device__ __align__(16) float g_h[NN * DIM];        // node features after w_in
__device__ __align__(16) float g_su[NN * HEADS];
__device__ __align__(16) float g_sv[NN * HEADS];
__device__ __align__(16) float g_denom[NN * HEADS];  // softmax denominators (unnormalized)
__device__ __align__(16) float g_aggr[NN * DIM];     // unnormalized weighted message sums
__device__ float g_W2[2 * HEADS];                    // w_edge @ w_att_e  [2,8]
__device__ float g_c[HEADS];                         // b_edge @ w_att_e + b_att_e

// -------- tiny prep: fold edge-feature path into 2x8 --------
__global__ void k_prep(const float* __restrict__ w_edge, const float* __restrict__ b_edge,
                       const float* __restrict__ w_att_e, const float* __restrict__ b_att_e) {
    int t = threadIdx.x;
    if (t < 16) {
        int i = t >> 3, hh = t & 7;
        float s = 0.f;
        for (int k = 0; k < DIM; k++) s = fmaf(w_edge[i * DIM + k], w_att_e[k * HEADS + hh], s);
        g_W2[t] = s;
    } else if (t < 24) {
        int hh = t - 16;
        float s = b_att_e[hh];
        for (int k = 0; k < DIM; k++) s = fmaf(b_edge[k], w_att_e[k * HEADS + hh], s);
        g_c[hh] = s;
    }
}

// -------- node input: h = x@w_in + b_in ; su = h@w_att_u + b ; sv = h@w_att_v --------
__global__ __launch_bounds__(256) void k_node_in(
    const float* __restrict__ x, const float* __restrict__ w_in, const float* __restrict__ b_in,
    const float* __restrict__ wu, const float* __restrict__ bu, const float* __restrict__ wv) {
    __shared__ float xs[4 * DIM];
    __shared__ float hs[4 * DIM];
    __shared__ float wus[DIM * HEADS];
    __shared__ float wvs[DIM * HEADS];

    int t = threadIdx.x;
    int nd = t >> 6, j = t & 63;

    for (int i = t; i < DIM * HEADS; i += 256) { wus[i] = wu[i]; wvs[i] = wv[i]; }

    float wcol[DIM];
#pragma unroll
    for (int k = 0; k < DIM; k++) wcol[k] = w_in[k * DIM + j];
    float bj = b_in[j];
    __syncthreads();

    int ngroups = (NN + 3) / 4;
    for (int g = blockIdx.x; g < ngroups; g += gridDim.x) {
        int n = g * 4 + nd;
        if (n < NN) xs[nd * DIM + j] = x[n * DIM + j];
        __syncthreads();
        if (n < NN) {
            float acc = bj;
            const float4* xp = (const float4*)(xs + nd * DIM);
#pragma unroll
            for (int k4 = 0; k4 < 16; k4++) {
                float4 xv = xp[k4];
                acc = fmaf(xv.x, wcol[4 * k4 + 0], acc);
                acc = fmaf(xv.y, wcol[4 * k4 + 1], acc);
                acc = fmaf(xv.z, wcol[4 * k4 + 2], acc);
                acc = fmaf(xv.w, wcol[4 * k4 + 3], acc);
            }
            hs[nd * DIM + j] = acc;
            g_h[n * DIM + j] = acc;
        }
        __syncthreads();
        if (n < NN && j < 16) {
            int hh = j & 7;
            const float* wm = (j < 8) ? wus : wvs;
            float s = (j < 8) ? bu[hh] : 0.f;
#pragma unroll 8
            for (int k = 0; k < DIM; k++) s = fmaf(hs[nd * DIM + k], wm[k * HEADS + hh], s);
            if (j < 8) g_su[n * HEADS + hh] = s;
            else       g_sv[n * HEADS + hh] = s;
        }
        __syncthreads();
    }
}

// -------- single edge pass: scores -> exp -> denom & weighted message scatter --------
__global__ __launch_bounds__(256) void k_edge(const int* __restrict__ src, const int* __restrict__ dst,
                                              const float* __restrict__ ef) {
    __shared__ float W2s[16];
    __shared__ float cs[8];
    if (threadIdx.x < 16) W2s[threadIdx.x] = g_W2[threadIdx.x];
    if (threadIdx.x < 8)  cs[threadIdx.x] = g_c[threadIdx.x];
    __syncthreads();

    for (int e = blockIdx.x * blockDim.x + threadIdx.x; e < EE; e += gridDim.x * blockDim.x) {
        int s = src[e], d = dst[e];
        float2 f = ((const float2*)ef)[e];
        const float4* sup = (const float4*)(g_su + s * HEADS);
        const float4* svp = (const float4*)(g_sv + d * HEADS);
        float4 u0 = sup[0], u1 = sup[1], v0 = svp[0], v1 = svp[1];
        float tt[8];
        tt[0] = u0.x + v0.x; tt[1] = u0.y + v0.y; tt[2] = u0.z + v0.z; tt[3] = u0.w + v0.w;
        tt[4] = u1.x + v1.x; tt[5] = u1.y + v1.y; tt[6] = u1.z + v1.z; tt[7] = u1.w + v1.w;
#pragma unroll
        for (int hh = 0; hh < 8; hh++) {
            float v = tt[hh] + f.x * W2s[hh] + f.y * W2s[8 + hh] + cs[hh];
            v = fmaxf(v, 0.2f * v);          // LeakyReLU(0.2)
            tt[hh] = __expf(v);              // no max-subtraction needed (small scores)
        }
        float4* dnp = (float4*)(g_denom + d * HEADS);
        atomicAdd(dnp + 0, make_float4(tt[0], tt[1], tt[2], tt[3]));
        atomicAdd(dnp + 1, make_float4(tt[4], tt[5], tt[6], tt[7]));

        const float4* hp = (const float4*)(g_h + s * DIM);
        float4* op = (float4*)(g_aggr + d * DIM);
#pragma unroll
        for (int q = 0; q < 16; q++) {
            float4 hv = hp[q];
            int b = (q & 1) * 4;  // head index = column & 7 (reshape [N, hd, H])
            atomicAdd(op + q, make_float4(hv.x * tt[b + 0], hv.y * tt[b + 1],
                                          hv.z * tt[b + 2], hv.w * tt[b + 3]));
        }
    }
}

// -------- normalize + FFN: out = gelu(agg@w1+b1)@w2 + b2 --------
// v2: 16 nodes / iteration, 2 blocks/SM. w1 read from L1 via __ldg (coalesced),
// w2 split-K columns in registers. FMA:LDS ratio 4:1 in both GEMMs.
#define FFN 16
__global__ __launch_bounds__(256, 2) void k_ff(
    const float* __restrict__ w1, const float* __restrict__ b1,
    const float* __restrict__ w2, const float* __restrict__ b2,
    float* __restrict__ out) {
    __shared__ float aggs[FFN * DIM];         // 4 KB
    __shared__ float hids[FFN * HIDDEN];      // 16 KB
    __shared__ float psum[4 * FFN * DIM];     // 16 KB
    __shared__ float b2s[DIM];

    int t = threadIdx.x;
    int j = t & 63, gq = t >> 6;

    // GEMM2 weight column (split-K chunk gq) in registers
    float w2reg[DIM];
#pragma unroll
    for (int k = 0; k < DIM; k++) w2reg[k] = w2[(gq * DIM + k) * DIM + j];
    float b1t = b1[t];
    if (t < DIM) b2s[t] = b2[t];
    __syncthreads();

    int ngroups = NN / FFN;  // 6250, exact
    for (int g = blockIdx.x; g < ngroups; g += gridDim.x) {
        int n0 = g * FFN;
        // load + normalize aggregated messages (coalesced)
#pragma unroll
        for (int r = 0; r < FFN * DIM / 256; r++) {
            int idx = t + r * 256;
            int nd = idx >> 6, jj = idx & 63;
            int n = n0 + nd;
            float dn = g_denom[n * HEADS + (jj & 7)];
            aggs[idx] = g_aggr[n * DIM + jj] / fmaxf(dn, 1e-12f);
        }
        __syncthreads();

        // GEMM1: hidden unit t for all 16 nodes; w1 column streamed from L1
        float hacc[FFN];
#pragma unroll
        for (int q = 0; q < FFN; q++) hacc[q] = b1t;
#pragma unroll
        for (int k4 = 0; k4 < 16; k4++) {
            float wa = __ldg(&w1[(4 * k4 + 0) * HIDDEN + t]);
            float wb = __ldg(&w1[(4 * k4 + 1) * HIDDEN + t]);
            float wc = __ldg(&w1[(4 * k4 + 2) * HIDDEN + t]);
            float wd = __ldg(&w1[(4 * k4 + 3) * HIDDEN + t]);
#pragma unroll
            for (int q = 0; q < FFN; q++) {
                float4 av = *(const float4*)(aggs + q * DIM + 4 * k4);
                hacc[q] = fmaf(av.x, wa, hacc[q]);
                hacc[q] = fmaf(av.y, wb, hacc[q]);
                hacc[q] = fmaf(av.z, wc, hacc[q]);
                hacc[q] = fmaf(av.w, wd, hacc[q]);
            }
        }
#pragma unroll
        for (int q = 0; q < FFN; q++) {
            float v = hacc[q];
            v = 0.5f * v * (1.0f + erff(v * 0.70710678118654752f));  // exact gelu
            hids[q * HIDDEN + t] = v;
        }
        __syncthreads();

        // GEMM2 (split-K over 4 groups of 64)
        float oacc[FFN];
#pragma unroll
        for (int q = 0; q < FFN; q++) oacc[q] = 0.f;
#pragma unroll
        for (int k4 = 0; k4 < 16; k4++) {
#pragma unroll
            for (int q = 0; q < FFN; q++) {
                float4 hv = *(const float4*)(hids + q * HIDDEN + gq * DIM + 4 * k4);
                oacc[q] = fmaf(hv.x, w2reg[4 * k4 + 0], oacc[q]);
                oacc[q] = fmaf(hv.y, w2reg[4 * k4 + 1], oacc[q]);
                oacc[q] = fmaf(hv.z, w2reg[4 * k4 + 2], oacc[q]);
                oacc[q] = fmaf(hv.w, w2reg[4 * k4 + 3], oacc[q]);
            }
        }
#pragma unroll
        for (int q = 0; q < FFN; q++) psum[(gq * FFN + q) * DIM + j] = oacc[q];
        __syncthreads();

        // reduce split-K partials and store (coalesced)
#pragma unroll
        for (int r = 0; r < FFN * DIM / 256; r++) {
            int idx = t + r * 256;
            int q = idx >> 6, jj = idx & 63;
            int n = n0 + q;
            float s = b2s[jj];
            s += psum[(0 * FFN + q) * DIM + jj];
            s += psum[(1 * FFN + q) * DIM + jj];
            s += psum[(2 * FFN + q) * DIM + jj];
            s += psum[(3 * FFN + q) * DIM + jj];
            out[n * DIM + jj] = s;
        }
        __syncthreads();
    }
}

extern "C" void kernel_launch(void* const* d_in, const int* in_sizes, int n_in,
                              void* d_out, int out_size) {
    const float* x       = (const float*)d_in[0];
    const float* ef      = (const float*)d_in[1];
    const float* w_in    = (const float*)d_in[2];
    const float* b_in    = (const float*)d_in[3];
    const float* w_edge  = (const float*)d_in[4];
    const float* b_edge  = (const float*)d_in[5];
    const float* w_att_u = (const float*)d_in[6];
    const float* b_att_u = (const float*)d_in[7];
    const float* w_att_v = (const float*)d_in[8];
    const float* w_att_e = (const float*)d_in[9];
    const float* b_att_e = (const float*)d_in[10];
    const float* w_ff1   = (const float*)d_in[11];
    const float* b_ff1   = (const float*)d_in[12];
    const float* w_ff2   = (const float*)d_in[13];
    const float* b_ff2   = (const float*)d_in[14];
    const int*   src     = (const int*)d_in[15];
    const int*   dst     = (const int*)d_in[16];
    float* out = (float*)d_out;

    void *p_denom = nullptr, *p_aggr = nullptr;
    cudaGetSymbolAddress(&p_denom, g_denom);
    cudaGetSymbolAddress(&p_aggr, g_aggr);
    cudaMemsetAsync(p_denom, 0, (size_t)NN * HEADS * sizeof(float), 0);
    cudaMemsetAsync(p_aggr, 0, (size_t)NN * DIM * sizeof(float), 0);

    k_prep<<<1, 32>>>(w_edge, b_edge, w_att_e, b_att_e);
    k_node_in<<<2048, 256>>>(x, w_in, b_in, w_att_u, b_att_u, w_att_v);
    k_edge<<<(EE + 255) / 256, 256>>>(src, dst, ef);
    k_ff<<<296, 256>>>(w_ff1, b_ff1, w_ff2, b_ff2, out);
}

// round 3
// speedup vs baseline: 1.2675x; 1.1521x over previous
#include <cuda_runtime.h>
#include <cuda_bf16.h>
#include <math.h>

#define NN 100000
#define EE 1600000
#define DIM 64
#define HEADS 8
#define HIDDEN 256
#define NB 391   // ceil(NN/256)

// -------- scratch (device globals; no allocation allowed) --------
__device__ __align__(16) float g_h[NN * DIM];        // node features after w_in
__device__ __align__(16) float g_su[NN * HEADS];
__device__ __align__(16) float g_sv[NN * HEADS];
__device__ __align__(16) float g_aggr[NN * DIM];     // normalized attention output
__device__ float g_W2[2 * HEADS];                    // w_edge @ w_att_e  [2,8]
__device__ float g_c[HEADS];                         // b_edge @ w_att_e + b_att_e
// CSR build
__device__ int   g_deg[NN];
__device__ int   g_off[NN];
__device__ int   g_cur[NN];
__device__ int   g_bsum[512];
__device__ int   g_esrc[EE];
__device__ __align__(8) float2 g_eef[EE];

// fast exp: FFMA-only (scores are small; range reduction handles |x| up to ~80)
__device__ __forceinline__ float fexp(float x) {
    float t = x * 1.4426950408889634f;
    int i = __float2int_rn(t);
    float f = t - (float)i;
    float g = f * 0.6931471805599453f;   // |g| <= 0.347
    float p = 8.3333337676e-3f;          // exp(g) Taylor deg-5
    p = fmaf(p, g, 4.1666668654e-2f);
    p = fmaf(p, g, 1.6666667163e-1f);
    p = fmaf(p, g, 5.0000000000e-1f);
    p = fmaf(p, g, 1.0f);
    p = fmaf(p, g, 1.0f);
    return __int_as_float(__float_as_int(p) + (i << 23));
}

// -------- tiny prep: fold edge-feature path into 2x8 --------
__global__ void k_prep(const float* __restrict__ w_edge, const float* __restrict__ b_edge,
                       const float* __restrict__ w_att_e, const float* __restrict__ b_att_e) {
    int t = threadIdx.x;
    if (t < 16) {
        int i = t >> 3, hh = t & 7;
        float s = 0.f;
        for (int k = 0; k < DIM; k++) s = fmaf(w_edge[i * DIM + k], w_att_e[k * HEADS + hh], s);
        g_W2[t] = s;
    } else if (t < 24) {
        int hh = t - 16;
        float s = b_att_e[hh];
        for (int k = 0; k < DIM; k++) s = fmaf(b_edge[k], w_att_e[k * HEADS + hh], s);
        g_c[hh] = s;
    }
}

// -------- node input: h = x@w_in + b_in ; su = h@w_att_u + b ; sv = h@w_att_v --------
__global__ __launch_bounds__(256) void k_node_in(
    const float* __restrict__ x, const float* __restrict__ w_in, const float* __restrict__ b_in,
    const float* __restrict__ wu, const float* __restrict__ bu, const float* __restrict__ wv) {
    __shared__ float xs[4 * DIM];
    __shared__ float hs[4 * DIM];
    __shared__ float wus[DIM * HEADS];
    __shared__ float wvs[DIM * HEADS];

    int t = threadIdx.x;
    int nd = t >> 6, j = t & 63;

    for (int i = t; i < DIM * HEADS; i += 256) { wus[i] = wu[i]; wvs[i] = wv[i]; }

    float wcol[DIM];
#pragma unroll
    for (int k = 0; k < DIM; k++) wcol[k] = w_in[k * DIM + j];
    float bj = b_in[j];
    __syncthreads();

    int ngroups = (NN + 3) / 4;
    for (int g = blockIdx.x; g < ngroups; g += gridDim.x) {
        int n = g * 4 + nd;
        if (n < NN) xs[nd * DIM + j] = x[n * DIM + j];
        __syncthreads();
        if (n < NN) {
            float acc = bj;
            const float4* xp = (const float4*)(xs + nd * DIM);
#pragma unroll
            for (int k4 = 0; k4 < 16; k4++) {
                float4 xv = xp[k4];
                acc = fmaf(xv.x, wcol[4 * k4 + 0], acc);
                acc = fmaf(xv.y, wcol[4 * k4 + 1], acc);
                acc = fmaf(xv.z, wcol[4 * k4 + 2], acc);
                acc = fmaf(xv.w, wcol[4 * k4 + 3], acc);
            }
            hs[nd * DIM + j] = acc;
            g_h[n * DIM + j] = acc;
        }
        __syncthreads();
        if (n < NN && j < 16) {
            int hh = j & 7;
            const float* wm = (j < 8) ? wus : wvs;
            float s = (j < 8) ? bu[hh] : 0.f;
#pragma unroll 8
            for (int k = 0; k < DIM; k++) s = fmaf(hs[nd * DIM + k], wm[k * HEADS + hh], s);
            if (j < 8) g_su[n * HEADS + hh] = s;
            else       g_sv[n * HEADS + hh] = s;
        }
        __syncthreads();
    }
}

// -------- CSR build --------
__global__ __launch_bounds__(256) void k_hist(const int* __restrict__ dst) {
    for (int e = blockIdx.x * 256 + threadIdx.x; e < EE; e += gridDim.x * 256)
        atomicAdd(&g_deg[dst[e]], 1);
}

__global__ __launch_bounds__(256) void k_scan_part() {
    __shared__ int s[256];
    int t = threadIdx.x;
    int i = blockIdx.x * 256 + t;
    s[t] = (i < NN) ? g_deg[i] : 0;
    __syncthreads();
    for (int ofs = 128; ofs > 0; ofs >>= 1) {
        if (t < ofs) s[t] += s[t + ofs];
        __syncthreads();
    }
    if (t == 0) g_bsum[blockIdx.x] = s[0];
}

__global__ __launch_bounds__(512) void k_scan_top() {
    __shared__ int s[512];
    int t = threadIdx.x;
    int v = (t < NB) ? g_bsum[t] : 0;
    s[t] = v;
    __syncthreads();
    for (int ofs = 1; ofs < 512; ofs <<= 1) {
        int add = (t >= ofs) ? s[t - ofs] : 0;
        __syncthreads();
        s[t] += add;
        __syncthreads();
    }
    if (t < NB) g_bsum[t] = s[t] - v;   // exclusive
}

__global__ __launch_bounds__(256) void k_scan_final() {
    __shared__ int s[256];
    int t = threadIdx.x;
    int i = blockIdx.x * 256 + t;
    int v = (i < NN) ? g_deg[i] : 0;
    s[t] = v;
    __syncthreads();
    for (int ofs = 1; ofs < 256; ofs <<= 1) {
        int add = (t >= ofs) ? s[t - ofs] : 0;
        __syncthreads();
        s[t] += add;
        __syncthreads();
    }
    if (i < NN) {
        int excl = s[t] - v + g_bsum[blockIdx.x];
        g_off[i] = excl;
        g_cur[i] = excl;
    }
}

__global__ __launch_bounds__(256) void k_scatter(const int* __restrict__ src,
                                                const int* __restrict__ dst,
                                                const float* __restrict__ ef) {
    for (int e = blockIdx.x * 256 + threadIdx.x; e < EE; e += gridDim.x * 256) {
        int d = dst[e];
        int p = atomicAdd(&g_cur[d], 1);
        g_esrc[p] = src[e];
        g_eef[p] = ((const float2*)ef)[e];
    }
}

// -------- gather-aggregate: one warp per dst node, no atomics --------
__global__ __launch_bounds__(256) void k_aggr() {
    int n = (blockIdx.x * 256 + threadIdx.x) >> 5;
    if (n >= NN) return;
    int lane = threadIdx.x & 31;
    int hh = lane & 7;

    float w2x = g_W2[hh], w2y = g_W2[8 + hh], cc = g_c[hh];
    float svv = g_sv[n * HEADS + hh];
    int beg = g_off[n], cnt = g_deg[n];

    float acc0 = 0.f, acc1 = 0.f, dsum = 0.f;
    if (cnt > 0) {
        int s = g_esrc[beg];
        float2 f = g_eef[beg];
        for (int it = 0; it < cnt; it++) {
            int sn = 0; float2 fn = make_float2(0.f, 0.f);
            if (it + 1 < cnt) { sn = g_esrc[beg + it + 1]; fn = g_eef[beg + it + 1]; }
            float sc = g_su[s * HEADS + hh] + svv + fmaf(f.x, w2x, fmaf(f.y, w2y, cc));
            sc = fmaxf(sc, 0.2f * sc);          // LeakyReLU(0.2)
            float tt = fexp(sc);
            dsum += tt;
            acc0 = fmaf(g_h[s * DIM + lane], tt, acc0);
            acc1 = fmaf(g_h[s * DIM + 32 + lane], tt, acc1);
            s = sn; f = fn;
        }
    }
    float inv = 1.f / fmaxf(dsum, 1e-12f);
    g_aggr[n * DIM + lane]      = acc0 * inv;
    g_aggr[n * DIM + 32 + lane] = acc1 * inv;
}

// -------- FFN: out = gelu(agg@w1+b1)@w2 + b2 (agg pre-normalized) --------
#define FFN 16
__global__ __launch_bounds__(256, 2) void k_ff(
    const float* __restrict__ w1, const float* __restrict__ b1,
    const float* __restrict__ w2, const float* __restrict__ b2,
    float* __restrict__ out) {
    __shared__ float aggs[FFN * DIM];
    __shared__ float hids[FFN * HIDDEN];
    __shared__ float psum[4 * FFN * DIM];
    __shared__ float b2s[DIM];

    int t = threadIdx.x;
    int j = t & 63, gq = t >> 6;

    float w2reg[DIM];
#pragma unroll
    for (int k = 0; k < DIM; k++) w2reg[k] = w2[(gq * DIM + k) * DIM + j];
    float b1t = b1[t];
    if (t < DIM) b2s[t] = b2[t];
    __syncthreads();

    int ngroups = NN / FFN;  // 6250 exact
    for (int g = blockIdx.x; g < ngroups; g += gridDim.x) {
        int n0 = g * FFN;
#pragma unroll
        for (int r = 0; r < FFN * DIM / 256; r++) {
            int idx = t + r * 256;
            aggs[idx] = g_aggr[n0 * DIM + idx];
        }
        __syncthreads();

        float hacc[FFN];
#pragma unroll
        for (int q = 0; q < FFN; q++) hacc[q] = b1t;
#pragma unroll
        for (int k4 = 0; k4 < 16; k4++) {
            float wa = __ldg(&w1[(4 * k4 + 0) * HIDDEN + t]);
            float wb = __ldg(&w1[(4 * k4 + 1) * HIDDEN + t]);
            float wc = __ldg(&w1[(4 * k4 + 2) * HIDDEN + t]);
            float wd = __ldg(&w1[(4 * k4 + 3) * HIDDEN + t]);
#pragma unroll
            for (int q = 0; q < FFN; q++) {
                float4 av = *(const float4*)(aggs + q * DIM + 4 * k4);
                hacc[q] = fmaf(av.x, wa, hacc[q]);
                hacc[q] = fmaf(av.y, wb, hacc[q]);
                hacc[q] = fmaf(av.z, wc, hacc[q]);
                hacc[q] = fmaf(av.w, wd, hacc[q]);
            }
        }
#pragma unroll
        for (int q = 0; q < FFN; q++) {
            float v = hacc[q];
            v = 0.5f * v * (1.0f + erff(v * 0.70710678118654752f));
            hids[q * HIDDEN + t] = v;
        }
        __syncthreads();

        float oacc[FFN];
#pragma unroll
        for (int q = 0; q < FFN; q++) oacc[q] = 0.f;
#pragma unroll
        for (int k4 = 0; k4 < 16; k4++) {
#pragma unroll
            for (int q = 0; q < FFN; q++) {
                float4 hv = *(const float4*)(hids + q * HIDDEN + gq * DIM + 4 * k4);
                oacc[q] = fmaf(hv.x, w2reg[4 * k4 + 0], oacc[q]);
                oacc[q] = fmaf(hv.y, w2reg[4 * k4 + 1], oacc[q]);
                oacc[q] = fmaf(hv.z, w2reg[4 * k4 + 2], oacc[q]);
                oacc[q] = fmaf(hv.w, w2reg[4 * k4 + 3], oacc[q]);
            }
        }
#pragma unroll
        for (int q = 0; q < FFN; q++) psum[(gq * FFN + q) * DIM + j] = oacc[q];
        __syncthreads();

#pragma unroll
        for (int r = 0; r < FFN * DIM / 256; r++) {
            int idx = t + r * 256;
            int q = idx >> 6, jj = idx & 63;
            float s = b2s[jj];
            s += psum[(0 * FFN + q) * DIM + jj];
            s += psum[(1 * FFN + q) * DIM + jj];
            s += psum[(2 * FFN + q) * DIM + jj];
            s += psum[(3 * FFN + q) * DIM + jj];
            out[(n0 + q) * DIM + jj] = s;
        }
        __syncthreads();
    }
}

extern "C" void kernel_launch(void* const* d_in, const int* in_sizes, int n_in,
                              void* d_out, int out_size) {
    const float* x       = (const float*)d_in[0];
    const float* ef      = (const float*)d_in[1];
    const float* w_in    = (const float*)d_in[2];
    const float* b_in    = (const float*)d_in[3];
    const float* w_edge  = (const float*)d_in[4];
    const float* b_edge  = (const float*)d_in[5];
    const float* w_att_u = (const float*)d_in[6];
    const float* b_att_u = (const float*)d_in[7];
    const float* w_att_v = (const float*)d_in[8];
    const float* w_att_e = (const float*)d_in[9];
    const float* b_att_e = (const float*)d_in[10];
    const float* w_ff1   = (const float*)d_in[11];
    const float* b_ff1   = (const float*)d_in[12];
    const float* w_ff2   = (const float*)d_in[13];
    const float* b_ff2   = (const float*)d_in[14];
    const int*   src     = (const int*)d_in[15];
    const int*   dst     = (const int*)d_in[16];
    float* out = (float*)d_out;

    void* p_deg = nullptr;
    cudaGetSymbolAddress(&p_deg, g_deg);
    cudaMemsetAsync(p_deg, 0, (size_t)NN * sizeof(int), 0);

    k_prep<<<1, 32>>>(w_edge, b_edge, w_att_e, b_att_e);
    k_node_in<<<2048, 256>>>(x, w_in, b_in, w_att_u, b_att_u, w_att_v);
    k_hist<<<1184, 256>>>(dst);
    k_scan_part<<<NB, 256>>>();
    k_scan_top<<<1, 512>>>();
    k_scan_final<<<NB, 256>>>();
    k_scatter<<<1184, 256>>>(src, dst, ef);
    k_aggr<<<(NN * 32 + 255) / 256, 256>>>();
    k_ff<<<296, 256>>>(w_ff1, b_ff1, w_ff2, b_ff2, out);
}

// round 5
// speedup vs baseline: 1.7671x; 1.3942x over previous
#include <cuda_runtime.h>
#include <cuda_bf16.h>
#include <math.h>
#include <stdint.h>

#define NN 100000
#define EE 1600000
#define DIM 64
#define HEADS 8
#define HIDDEN 256
#define NB 391   // ceil(NN/256)

// -------- scratch (device globals; no allocation allowed) --------
__device__ __align__(16) float g_h[NN * DIM];
__device__ __align__(16) float g_su[NN * HEADS];
__device__ __align__(16) float g_sv[NN * HEADS];
__device__ __align__(16) float g_aggr[NN * DIM];
__device__ float g_W2[2 * HEADS];
__device__ float g_c[HEADS];
__device__ int   g_deg[NN];
__device__ int   g_off[NN];
__device__ int   g_cur[NN];
__device__ int   g_bsum[512];
__device__ int   g_esrc[EE];
__device__ __align__(8) float2 g_eef[EE];

// fast exp (FFMA-only)
__device__ __forceinline__ float fexp(float x) {
    float t = x * 1.4426950408889634f;
    int i = __float2int_rn(t);
    float f = t - (float)i;
    float g = f * 0.6931471805599453f;
    float p = 8.3333337676e-3f;
    p = fmaf(p, g, 4.1666668654e-2f);
    p = fmaf(p, g, 1.6666667163e-1f);
    p = fmaf(p, g, 5.0000000000e-1f);
    p = fmaf(p, g, 1.0f);
    p = fmaf(p, g, 1.0f);
    return __int_as_float(__float_as_int(p) + (i << 23));
}

__device__ __forceinline__ uint32_t to_tf32(float f) {
    uint32_t r;
    asm("cvt.rna.tf32.f32 %0, %1;" : "=r"(r) : "f"(f));
    return r;
}

// -------- tiny prep --------
__global__ void k_prep(const float* __restrict__ w_edge, const float* __restrict__ b_edge,
                       const float* __restrict__ w_att_e, const float* __restrict__ b_att_e) {
    int t = threadIdx.x;
    if (t < 16) {
        int i = t >> 3, hh = t & 7;
        float s = 0.f;
        for (int k = 0; k < DIM; k++) s = fmaf(w_edge[i * DIM + k], w_att_e[k * HEADS + hh], s);
        g_W2[t] = s;
    } else if (t < 24) {
        int hh = t - 16;
        float s = b_att_e[hh];
        for (int k = 0; k < DIM; k++) s = fmaf(b_edge[k], w_att_e[k * HEADS + hh], s);
        g_c[hh] = s;
    }
}

// -------- node input --------
__global__ __launch_bounds__(256) void k_node_in(
    const float* __restrict__ x, const float* __restrict__ w_in, const float* __restrict__ b_in,
    const float* __restrict__ wu, const float* __restrict__ bu, const float* __restrict__ wv) {
    __shared__ float xs[4 * DIM];
    __shared__ float hs[4 * DIM];
    __shared__ float wus[DIM * HEADS];
    __shared__ float wvs[DIM * HEADS];

    int t = threadIdx.x;
    int nd = t >> 6, j = t & 63;
    for (int i = t; i < DIM * HEADS; i += 256) { wus[i] = wu[i]; wvs[i] = wv[i]; }

    float wcol[DIM];
#pragma unroll
    for (int k = 0; k < DIM; k++) wcol[k] = w_in[k * DIM + j];
    float bj = b_in[j];
    __syncthreads();

    int ngroups = (NN + 3) / 4;
    for (int g = blockIdx.x; g < ngroups; g += gridDim.x) {
        int n = g * 4 + nd;
        if (n < NN) xs[nd * DIM + j] = x[n * DIM + j];
        __syncthreads();
        if (n < NN) {
            float acc = bj;
            const float4* xp = (const float4*)(xs + nd * DIM);
#pragma unroll
            for (int k4 = 0; k4 < 16; k4++) {
                float4 xv = xp[k4];
                acc = fmaf(xv.x, wcol[4 * k4 + 0], acc);
                acc = fmaf(xv.y, wcol[4 * k4 + 1], acc);
                acc = fmaf(xv.z, wcol[4 * k4 + 2], acc);
                acc = fmaf(xv.w, wcol[4 * k4 + 3], acc);
            }
            hs[nd * DIM + j] = acc;
            g_h[n * DIM + j] = acc;
        }
        __syncthreads();
        if (n < NN && j < 16) {
            int hh = j & 7;
            const float* wm = (j < 8) ? wus : wvs;
            float s = (j < 8) ? bu[hh] : 0.f;
#pragma unroll 8
            for (int k = 0; k < DIM; k++) s = fmaf(hs[nd * DIM + k], wm[k * HEADS + hh], s);
            if (j < 8) g_su[n * HEADS + hh] = s;
            else       g_sv[n * HEADS + hh] = s;
        }
        __syncthreads();
    }
}

// -------- CSR build --------
__global__ __launch_bounds__(256) void k_hist(const int* __restrict__ dst) {
    for (int e = blockIdx.x * 256 + threadIdx.x; e < EE; e += gridDim.x * 256)
        atomicAdd(&g_deg[dst[e]], 1);
}
__global__ __launch_bounds__(256) void k_scan_part() {
    __shared__ int s[256];
    int t = threadIdx.x;
    int i = blockIdx.x * 256 + t;
    s[t] = (i < NN) ? g_deg[i] : 0;
    __syncthreads();
    for (int ofs = 128; ofs > 0; ofs >>= 1) {
        if (t < ofs) s[t] += s[t + ofs];
        __syncthreads();
    }
    if (t == 0) g_bsum[blockIdx.x] = s[0];
}
__global__ __launch_bounds__(512) void k_scan_top() {
    __shared__ int s[512];
    int t = threadIdx.x;
    int v = (t < NB) ? g_bsum[t] : 0;
    s[t] = v;
    __syncthreads();
    for (int ofs = 1; ofs < 512; ofs <<= 1) {
        int add = (t >= ofs) ? s[t - ofs] : 0;
        __syncthreads();
        s[t] += add;
        __syncthreads();
    }
    if (t < NB) g_bsum[t] = s[t] - v;
}
__global__ __launch_bounds__(256) void k_scan_final() {
    __shared__ int s[256];
    int t = threadIdx.x;
    int i = blockIdx.x * 256 + t;
    int v = (i < NN) ? g_deg[i] : 0;
    s[t] = v;
    __syncthreads();
    for (int ofs = 1; ofs < 256; ofs <<= 1) {
        int add = (t >= ofs) ? s[t - ofs] : 0;
        __syncthreads();
        s[t] += add;
        __syncthreads();
    }
    if (i < NN) {
        int excl = s[t] - v + g_bsum[blockIdx.x];
        g_off[i] = excl;
        g_cur[i] = excl;
    }
}
__global__ __launch_bounds__(256) void k_scatter(const int* __restrict__ src,
                                                const int* __restrict__ dst,
                                                const float* __restrict__ ef) {
    for (int e = blockIdx.x * 256 + threadIdx.x; e < EE; e += gridDim.x * 256) {
        int d = dst[e];
        int p = atomicAdd(&g_cur[d], 1);
        g_esrc[p] = src[e];
        g_eef[p] = ((const float2*)ef)[e];
    }
}

// -------- gather-aggregate: one warp per dst node --------
__global__ __launch_bounds__(256) void k_aggr() {
    int n = (blockIdx.x * 256 + threadIdx.x) >> 5;
    if (n >= NN) return;
    int lane = threadIdx.x & 31;
    int hh = lane & 7;

    float w2x = g_W2[hh], w2y = g_W2[8 + hh], cc = g_c[hh];
    float svv = g_sv[n * HEADS + hh];
    int beg = g_off[n], cnt = g_deg[n];

    float acc0 = 0.f, acc1 = 0.f, dsum = 0.f;
    if (cnt > 0) {
        int s = g_esrc[beg];
        float2 f = g_eef[beg];
        for (int it = 0; it < cnt; it++) {
            int sn = 0; float2 fn = make_float2(0.f, 0.f);
            if (it + 1 < cnt) { sn = g_esrc[beg + it + 1]; fn = g_eef[beg + it + 1]; }
            float sc = g_su[s * HEADS + hh] + svv + fmaf(f.x, w2x, fmaf(f.y, w2y, cc));
            sc = fmaxf(sc, 0.2f * sc);
            float tt = fexp(sc);
            dsum += tt;
            acc0 = fmaf(g_h[s * DIM + lane], tt, acc0);
            acc1 = fmaf(g_h[s * DIM + 32 + lane], tt, acc1);
            s = sn; f = fn;
        }
    }
    float inv = 1.f / fmaxf(dsum, 1e-12f);
    g_aggr[n * DIM + lane]      = acc0 * inv;
    g_aggr[n * DIM + 32 + lane] = acc1 * inv;
}

// ======== FFN via mma.sync tf32 (HMMA): out = gelu(agg@w1+b1)@w2 + b2 ========
// smem float offsets
#define PA  68              // A / hid row pitch
#define PB2 260             // B2t row pitch
#define OF_A   0                         // A: 128 x PA
#define OF_B1  (OF_A + 128 * PA)         // B1t: 256 x PA  (w1^T, [n][k])
#define OF_HID (OF_B1 + 256 * PA)        // hid chunk: 128 x PA
#define OF_B2  (OF_HID + 128 * PA)       // B2t: 64 x PB2  (w2^T, [n][k])
#define OF_BV1 (OF_B2 + 64 * PB2)        // b1: 256
#define OF_BV2 (OF_BV1 + 256)            // b2: 64
#define SMF_TOTAL (OF_BV2 + 64)          // floats
#define NTILES ((NN + 127) / 128)        // 782

#define MMA_TF32(c, a, b0v, b1v) \
    asm volatile("mma.sync.aligned.m16n8k8.row.col.f32.tf32.tf32.f32 " \
        "{%0,%1,%2,%3}, {%4,%5,%6,%7}, {%8,%9}, {%0,%1,%2,%3};" \
        : "+f"((c)[0]), "+f"((c)[1]), "+f"((c)[2]), "+f"((c)[3]) \
        : "r"((a)[0]), "r"((a)[1]), "r"((a)[2]), "r"((a)[3]), "r"(b0v), "r"(b1v))

__global__ __launch_bounds__(256, 1) void k_ffn_mma(
    const float* __restrict__ w1, const float* __restrict__ b1,
    const float* __restrict__ w2, const float* __restrict__ b2,
    float* __restrict__ out) {
    extern __shared__ float sm[];
    uint32_t* Au  = (uint32_t*)(sm + OF_A);
    uint32_t* B1u = (uint32_t*)(sm + OF_B1);
    uint32_t* Hu  = (uint32_t*)(sm + OF_HID);
    uint32_t* B2u = (uint32_t*)(sm + OF_B2);
    float* b1s = sm + OF_BV1;
    float* b2s = sm + OF_BV2;

    int t = threadIdx.x;
    int w = t >> 5, lane = t & 31;
    int gid = lane >> 2, tig = lane & 3;
    int arow = w * 16 + gid;          // this thread's base M row (and +8)

    // --- stage weights (once per CTA) ---
    b1s[t] = b1[t];
    if (t < 64) b2s[t] = b2[t];
#pragma unroll
    for (int i = 0; i < 64; i++) {            // w1 [64,256] -> B1t[n][k]
        int idx = t + i * 256;
        int k = idx >> 8, n = idx & 255;
        B1u[n * PA + k] = to_tf32(w1[idx]);
    }
#pragma unroll
    for (int i = 0; i < 64; i++) {            // w2 [256,64] -> B2t[n][k]
        int idx = t + i * 256;
        int k = idx >> 6, n = idx & 63;
        B2u[n * PB2 + k] = to_tf32(w2[idx]);
    }
    __syncthreads();

    for (int tile = blockIdx.x; tile < NTILES; tile += gridDim.x) {
        int n0 = tile * 128;
        // --- load A tile [128 x 64] (tf32-truncated) ---
#pragma unroll
        for (int i = 0; i < 32; i++) {
            int idx = t + i * 256;
            int row = idx >> 6, kf = idx & 63;
            int node = n0 + row;
            float v = (node < NN) ? g_aggr[node * DIM + kf] : 0.f;
            Au[row * PA + kf] = to_tf32(v);
        }
        __syncthreads();

        // --- preload A1 fragments for all 8 k-steps ---
        uint32_t af[8][4];
#pragma unroll
        for (int k = 0; k < 8; k++) {
            int base = arow * PA + k * 8 + tig;
            af[k][0] = Au[base];
            af[k][1] = Au[base + 8 * PA];
            af[k][2] = Au[base + 4];
            af[k][3] = Au[base + 8 * PA + 4];
        }

        float c2[8][4];
#pragma unroll
        for (int nt = 0; nt < 8; nt++)
#pragma unroll
            for (int q = 0; q < 4; q++) c2[nt][q] = 0.f;

        // --- 4 hidden chunks of 64 ---
#pragma unroll
        for (int ch = 0; ch < 4; ch++) {
            int hc0 = ch * 64;
            float c1[8][4];
#pragma unroll
            for (int nt = 0; nt < 8; nt++)
#pragma unroll
                for (int q = 0; q < 4; q++) c1[nt][q] = 0.f;

            // GEMM1: C1[128,64] = A[128,64] @ w1[:, hc0:hc0+64]
#pragma unroll
            for (int nt = 0; nt < 8; nt++) {
                int nb = (hc0 + nt * 8 + gid) * PA + tig;
#pragma unroll
                for (int k = 0; k < 8; k++) {
                    uint32_t b0v = B1u[nb + k * 8];
                    uint32_t b1v = B1u[nb + k * 8 + 4];
                    MMA_TF32(c1[nt], af[k], b0v, b1v);
                }
            }
            // bias + gelu -> hid smem (tf32)
#pragma unroll
            for (int nt = 0; nt < 8; nt++) {
                int cl = nt * 8 + 2 * tig;            // local col in chunk
                int cg = hc0 + cl;                    // global hidden col
                float bb0 = b1s[cg], bb1 = b1s[cg + 1];
#pragma unroll
                for (int q = 0; q < 4; q++) {
                    int rr = arow + (q >> 1) * 8;
                    float v = c1[nt][q] + ((q & 1) ? bb1 : bb0);
                    v = 0.5f * v * (1.0f + erff(v * 0.70710678118654752f));
                    Hu[rr * PA + cl + (q & 1)] = to_tf32(v);
                }
            }
            __syncthreads();

            // GEMM2 accumulate: C2 += hid[128,64] @ w2[hc0:hc0+64, :]
#pragma unroll
            for (int k2 = 0; k2 < 8; k2++) {
                uint32_t a2[4];
                int base = arow * PA + k2 * 8 + tig;
                a2[0] = Hu[base];
                a2[1] = Hu[base + 8 * PA];
                a2[2] = Hu[base + 4];
                a2[3] = Hu[base + 8 * PA + 4];
#pragma unroll
                for (int nt = 0; nt < 8; nt++) {
                    int bb = (nt * 8 + gid) * PB2 + hc0 + k2 * 8 + tig;
                    uint32_t b0v = B2u[bb];
                    uint32_t b1v = B2u[bb + 4];
                    MMA_TF32(c2[nt], a2, b0v, b1v);
                }
            }
            __syncthreads();
        }

        // --- epilogue: C2 + b2 -> out (paired 8B stores) ---
#pragma unroll
        for (int nt = 0; nt < 8; nt++) {
            int col = nt * 8 + 2 * tig;
            float bb0 = b2s[col], bb1 = b2s[col + 1];
            int nA = n0 + arow, nB = n0 + arow + 8;
            if (nA < NN) {
                float2 v = make_float2(c2[nt][0] + bb0, c2[nt][1] + bb1);
                *(float2*)(out + nA * DIM + col) = v;
            }
            if (nB < NN) {
                float2 v = make_float2(c2[nt][2] + bb0, c2[nt][3] + bb1);
                *(float2*)(out + nB * DIM + col) = v;
            }
        }
        __syncthreads();   // before next tile's A overwrite
    }
}

extern "C" void kernel_launch(void* const* d_in, const int* in_sizes, int n_in,
                              void* d_out, int out_size) {
    const float* x       = (const float*)d_in[0];
    const float* ef      = (const float*)d_in[1];
    const float* w_in    = (const float*)d_in[2];
    const float* b_in    = (const float*)d_in[3];
    const float* w_edge  = (const float*)d_in[4];
    const float* b_edge  = (const float*)d_in[5];
    const float* w_att_u = (const float*)d_in[6];
    const float* b_att_u = (const float*)d_in[7];
    const float* w_att_v = (const float*)d_in[8];
    const float* w_att_e = (const float*)d_in[9];
    const float* b_att_e = (const float*)d_in[10];
    const float* w_ff1   = (const float*)d_in[11];
    const float* b_ff1   = (const float*)d_in[12];
    const float* w_ff2   = (const float*)d_in[13];
    const float* b_ff2   = (const float*)d_in[14];
    const int*   src     = (const int*)d_in[15];
    const int*   dst     = (const int*)d_in[16];
    float* out = (float*)d_out;

    cudaFuncSetAttribute(k_ffn_mma, cudaFuncAttributeMaxDynamicSharedMemorySize,
                         SMF_TOTAL * (int)sizeof(float));

    void* p_deg = nullptr;
    cudaGetSymbolAddress(&p_deg, g_deg);
    cudaMemsetAsync(p_deg, 0, (size_t)NN * sizeof(int), 0);

    k_prep<<<1, 32>>>(w_edge, b_edge, w_att_e, b_att_e);
    k_node_in<<<2048, 256>>>(x, w_in, b_in, w_att_u, b_att_u, w_att_v);
    k_hist<<<1184, 256>>>(dst);
    k_scan_part<<<NB, 256>>>();
    k_scan_top<<<1, 512>>>();
    k_scan_final<<<NB, 256>>>();
    k_scatter<<<1184, 256>>>(src, dst, ef);
    k_aggr<<<(NN * 32 + 255) / 256, 256>>>();
    k_ffn_mma<<<148, 256, SMF_TOTAL * sizeof(float)>>>(w_ff1, b_ff1, w_ff2, b_ff2, out);
}